// round 14
// baseline (speedup 1.0000x reference)
#include <cuda_runtime.h>
#include <cuda_fp16.h>

#define N_NODES 50000
#define N_EDGES 800000
#define D_FEAT  64
#define WARPS_PER_BLOCK 8
#define GRID_B 1184                            // 148 SMs x 8 resident blocks
#define CONV_THREADS (N_NODES * D_FEAT / 8)    // 400000

// Precomputed CSR row pointers.
__device__ int g_row_ptr[N_NODES + 1];
// fp16 copy of embeds: one 128B cache line per row. 6.4MB, L2-resident.
__device__ __half2 g_emb_h[N_NODES * D_FEAT / 2];
// Dynamic work ticket (reset by prep each launch/replay).
__device__ unsigned g_ticket;

// Fused prep: ticket reset + O(E) scatter row_ptr build + fp32->fp16 convert.
__global__ __launch_bounds__(256)
void prep_kernel(const int* __restrict__ row_idx,
                 const float* __restrict__ embeds) {
    const int t = blockIdx.x * blockDim.x + threadIdx.x;
    if (t == 0) g_ticket = 0u;

    if (t <= N_EDGES) {
        if (t == 0) {
            const int r1 = __ldg(row_idx + 0);
            for (int r = 0; r <= r1; r++) g_row_ptr[r] = 0;
        } else {
            const int r0 = __ldg(row_idx + t - 1);
            const int r1 = (t < N_EDGES) ? __ldg(row_idx + t) : N_NODES;
            for (int r = r0 + 1; r <= r1; r++) g_row_ptr[r] = t;
        }
    }

    if (t < CONV_THREADS) {
        const float4* e4 = reinterpret_cast<const float4*>(embeds);
        const float4 a = __ldg(e4 + 2 * t);
        const float4 b = __ldg(e4 + 2 * t + 1);
        __half2* dst = g_emb_h + 4 * t;
        dst[0] = __float22half2_rn(make_float2(a.x, a.y));
        dst[1] = __float22half2_rn(make_float2(a.z, a.w));
        dst[2] = __float22half2_rn(make_float2(b.x, b.y));
        dst[3] = __float22half2_rn(make_float2(b.z, b.w));
    }
}

// Packed f32x2 helpers.
__device__ __forceinline__ unsigned long long pk2(float lo, float hi) {
    unsigned long long r;
    asm("mov.b64 %0, {%1, %2};" : "=l"(r) : "f"(lo), "f"(hi));
    return r;
}
__device__ __forceinline__ void ffma2(unsigned long long& acc,
                                      unsigned long long x,
                                      unsigned long long v) {
    asm("fma.rn.f32x2 %0, %1, %2, %3;" : "=l"(acc) : "l"(x), "l"(v), "l"(acc));
}
__device__ __forceinline__ float2 unpk2(unsigned long long p) {
    float2 f;
    asm("mov.b64 {%0, %1}, %2;" : "=f"(f.x), "=f"(f.y) : "l"(p));
    return f;
}

// Accumulate one fp16 embed row slice (uint4 = 8 halves) times v.
__device__ __forceinline__ void acc_edge(unsigned long long& A0,
                                         unsigned long long& A1,
                                         unsigned long long& A2,
                                         unsigned long long& A3,
                                         uint4 x, float v) {
    const unsigned long long vv = pk2(v, v);
    float2 f;
    f = __half22float2(*reinterpret_cast<const __half2*>(&x.x));
    ffma2(A0, pk2(f.x, f.y), vv);
    f = __half22float2(*reinterpret_cast<const __half2*>(&x.y));
    ffma2(A1, pk2(f.x, f.y), vv);
    f = __half22float2(*reinterpret_cast<const __half2*>(&x.z));
    ffma2(A2, pk2(f.x, f.y), vv);
    f = __half22float2(*reinterpret_cast<const __half2*>(&x.w));
    ffma2(A3, pk2(f.x, f.y), vv);
}

// Kernel B: persistent single-wave, dynamic warp tickets (8 rows each,
// 2 per quarter-warp). Quarter-warp per row: 8 lanes x uint4 = full 128B fp16
// row = one cache line per gather; lane-local accumulators; direct store.
__global__ __launch_bounds__(WARPS_PER_BLOCK * 32)
void gcn_spmm_kernel(const int* __restrict__ col_idx,
                     const float* __restrict__ vals,
                     float* __restrict__ out) {
    const int lane = threadIdx.x & 31;
    const int q8   = lane >> 3;                  // quarter id 0..3
    const int q    = lane & 7;                   // dim slice within row

    const uint4* __restrict__ emb16 = reinterpret_cast<const uint4*>(g_emb_h);

    for (;;) {
        unsigned base = 0;
        if (lane == 0) base = atomicAdd(&g_ticket, 8u);
        base = __shfl_sync(0xffffffffu, base, 0);
        if (base >= N_NODES) break;              // 50000 % 8 == 0: no partials

        #pragma unroll 1
        for (int rr = 0; rr < 2; rr++) {
            const int row = (int)base + (rr << 2) + q8;
            const int start = __ldg(&g_row_ptr[row]);
            const int end   = __ldg(&g_row_ptr[row + 1]);

            unsigned long long A0 = 0ull, A1 = 0ull, A2 = 0ull, A3 = 0ull;

            int e = start;
            // Pair loop: 2 independent gathers in flight.
            for (; e + 2 <= end; e += 2) {
                const int c0 = __ldg(col_idx + e);
                const int c1 = __ldg(col_idx + e + 1);
                const uint4 x0 = __ldg(emb16 + (size_t)c0 * 8 + q);
                const uint4 x1 = __ldg(emb16 + (size_t)c1 * 8 + q);
                const float v0 = __ldg(vals + e);
                const float v1 = __ldg(vals + e + 1);
                acc_edge(A0, A1, A2, A3, x0, v0);
                acc_edge(A0, A1, A2, A3, x1, v1);
            }
            if (e < end) {
                const int c0 = __ldg(col_idx + e);
                const uint4 x0 = __ldg(emb16 + (size_t)c0 * 8 + q);
                const float v0 = __ldg(vals + e);
                acc_edge(A0, A1, A2, A3, x0, v0);
            }

            // Direct store: lane q writes floats [8q..8q+7]. No shuffles.
            const float2 u0 = unpk2(A0), u1 = unpk2(A1);
            const float2 u2 = unpk2(A2), u3 = unpk2(A3);
            float4* o4 =
                reinterpret_cast<float4*>(out + (size_t)row * D_FEAT + q * 8);
            o4[0] = make_float4(u0.x, u0.y, u1.x, u1.y);
            o4[1] = make_float4(u2.x, u2.y, u3.x, u3.y);
        }
    }
}

extern "C" void kernel_launch(void* const* d_in, const int* in_sizes, int n_in,
                              void* d_out, int out_size) {
    const int*   row_idx = (const int*)  d_in[0];
    const int*   col_idx = (const int*)  d_in[1];
    const float* vals    = (const float*)d_in[2];
    const float* embeds  = (const float*)d_in[3];
    float*       out     = (float*)d_out;

    prep_kernel<<<(N_EDGES + 1 + 255) / 256, 256>>>(row_idx, embeds);

    gcn_spmm_kernel<<<GRID_B, WARPS_PER_BLOCK * 32>>>(col_idx, vals, out);
}

// round 15
// speedup vs baseline: 1.1631x; 1.1631x over previous
#include <cuda_runtime.h>
#include <cuda_fp16.h>

#define N_NODES 50000
#define N_EDGES 800000
#define D_FEAT  64
#define WARPS_PER_BLOCK 8
#define GRID_B 1184                             // 148 SMs x 8 blocks = 1 wave
#define NW (GRID_B * WARPS_PER_BLOCK)           // 9472 warps, edge-balanced
#define CONV_THREADS (N_NODES * D_FEAT / 8)     // 400000

// Precomputed CSR row pointers.
__device__ int g_row_ptr[N_NODES + 1];
// fp16 copy of embeds: one 128B cache line per row. 6.4MB, L2-resident.
__device__ uint4 g_emb_h[N_NODES * D_FEAT / 8];

// Fused prep: O(E) scatter row_ptr build + fp32->fp16 embed convert.
__global__ __launch_bounds__(256)
void prep_kernel(const int* __restrict__ row_idx,
                 const float* __restrict__ embeds) {
    const int t = blockIdx.x * blockDim.x + threadIdx.x;

    if (t <= N_EDGES) {
        if (t == 0) {
            const int r1 = __ldg(row_idx + 0);
            for (int r = 0; r <= r1; r++) g_row_ptr[r] = 0;
        } else {
            const int r0 = __ldg(row_idx + t - 1);
            const int r1 = (t < N_EDGES) ? __ldg(row_idx + t) : N_NODES;
            for (int r = r0 + 1; r <= r1; r++) g_row_ptr[r] = t;
        }
    }

    if (t < CONV_THREADS) {
        const float4* e4 = reinterpret_cast<const float4*>(embeds);
        const float4 a = __ldg(e4 + 2 * t);
        const float4 b = __ldg(e4 + 2 * t + 1);
        union { __half2 h[4]; uint4 u; } pk;
        pk.h[0] = __float22half2_rn(make_float2(a.x, a.y));
        pk.h[1] = __float22half2_rn(make_float2(a.z, a.w));
        pk.h[2] = __float22half2_rn(make_float2(b.x, b.y));
        pk.h[3] = __float22half2_rn(make_float2(b.z, b.w));
        g_emb_h[t] = pk.u;                       // single STG.128
    }
}

// Packed f32x2 helpers.
__device__ __forceinline__ unsigned long long pk2(float lo, float hi) {
    unsigned long long r;
    asm("mov.b64 %0, {%1, %2};" : "=l"(r) : "f"(lo), "f"(hi));
    return r;
}
__device__ __forceinline__ void ffma2(unsigned long long& acc,
                                      unsigned long long x,
                                      unsigned long long v) {
    asm("fma.rn.f32x2 %0, %1, %2, %3;" : "=l"(acc) : "l"(x), "l"(v), "l"(acc));
}
__device__ __forceinline__ float2 unpk2(unsigned long long p) {
    float2 f;
    asm("mov.b64 {%0, %1}, %2;" : "=f"(f.x), "=f"(f.y) : "l"(p));
    return f;
}

// Accumulate one fp16 embed row slice (uint4 = 8 halves) times v.
__device__ __forceinline__ void acc_edge(unsigned long long& A0,
                                         unsigned long long& A1,
                                         unsigned long long& A2,
                                         unsigned long long& A3,
                                         uint4 x, float v) {
    const unsigned long long vv = pk2(v, v);
    float2 f;
    f = __half22float2(*reinterpret_cast<const __half2*>(&x.x));
    ffma2(A0, pk2(f.x, f.y), vv);
    f = __half22float2(*reinterpret_cast<const __half2*>(&x.y));
    ffma2(A1, pk2(f.x, f.y), vv);
    f = __half22float2(*reinterpret_cast<const __half2*>(&x.z));
    ffma2(A2, pk2(f.x, f.y), vv);
    f = __half22float2(*reinterpret_cast<const __half2*>(&x.w));
    ffma2(A3, pk2(f.x, f.y), vv);
}

// Kernel B: edge-balanced static warp partition. Warp w owns rows whose
// FIRST edge is in [w*E/NW, (w+1)*E/NW) -- derived in-kernel from row_idx:
//   A_w = (e_w == 0) ? 0 : row_idx[e_w - 1] + 1,   A_NW = N_NODES.
// Rows are wholly owned (deterministic, no atomics). Each quarter-warp takes
// one row per pass: 8 lanes x uint4 = full 128B fp16 row = 1 cache line per
// gather; lane-local accumulators; direct coalesced store.
__global__ __launch_bounds__(WARPS_PER_BLOCK * 32, 8)
void gcn_spmm_kernel(const int* __restrict__ row_idx,
                     const int* __restrict__ col_idx,
                     const float* __restrict__ vals,
                     float* __restrict__ out) {
    const int lane = threadIdx.x & 31;
    const int q8   = lane >> 3;                  // quarter id 0..3
    const int q    = lane & 7;                   // dim slice within row
    const int w    = blockIdx.x * WARPS_PER_BLOCK + (threadIdx.x >> 5);

    // Edge-balanced row range for this warp.
    const long long e_lo = ((long long)w       * N_EDGES) / NW;
    const long long e_hi = ((long long)(w + 1) * N_EDGES) / NW;
    const int rowA = (e_lo == 0) ? 0 : __ldg(row_idx + (int)e_lo - 1) + 1;
    const int rowB = (w == NW - 1) ? N_NODES
                                   : ((e_hi == 0) ? 0
                                      : __ldg(row_idx + (int)e_hi - 1) + 1);

    for (int r0 = rowA; r0 < rowB; r0 += 4) {
        const int row = r0 + q8;
        const bool active = (row < rowB);
        // Inactive quarters run the loop zero times (start==end==0 via clamp).
        const int rclamp = active ? row : rowA;
        const int start  = active ? __ldg(&g_row_ptr[rclamp]) : 0;
        const int end    = active ? __ldg(&g_row_ptr[rclamp + 1]) : 0;

        unsigned long long A0 = 0ull, A1 = 0ull, A2 = 0ull, A3 = 0ull;

        int e = start;
        // Main: unguarded 4-edge chunks, 4 independent gathers in flight.
        for (; e + 4 <= end; e += 4) {
            const int c0 = __ldg(col_idx + e);
            const int c1 = __ldg(col_idx + e + 1);
            const int c2 = __ldg(col_idx + e + 2);
            const int c3 = __ldg(col_idx + e + 3);
            const uint4 x0 = __ldg(g_emb_h + (size_t)c0 * 8 + q);
            const uint4 x1 = __ldg(g_emb_h + (size_t)c1 * 8 + q);
            const uint4 x2 = __ldg(g_emb_h + (size_t)c2 * 8 + q);
            const uint4 x3 = __ldg(g_emb_h + (size_t)c3 * 8 + q);
            const float v0 = __ldg(vals + e);
            const float v1 = __ldg(vals + e + 1);
            const float v2 = __ldg(vals + e + 2);
            const float v3 = __ldg(vals + e + 3);
            acc_edge(A0, A1, A2, A3, x0, v0);
            acc_edge(A0, A1, A2, A3, x1, v1);
            acc_edge(A0, A1, A2, A3, x2, v2);
            acc_edge(A0, A1, A2, A3, x3, v3);
        }
        // Tail: <= 3 edges.
        for (; e < end; e++) {
            const int c0 = __ldg(col_idx + e);
            const uint4 x0 = __ldg(g_emb_h + (size_t)c0 * 8 + q);
            const float v0 = __ldg(vals + e);
            acc_edge(A0, A1, A2, A3, x0, v0);
        }

        if (active) {
            const float2 u0 = unpk2(A0), u1 = unpk2(A1);
            const float2 u2 = unpk2(A2), u3 = unpk2(A3);
            float4* o4 =
                reinterpret_cast<float4*>(out + (size_t)row * D_FEAT + q * 8);
            o4[0] = make_float4(u0.x, u0.y, u1.x, u1.y);
            o4[1] = make_float4(u2.x, u2.y, u3.x, u3.y);
        }
    }
}

extern "C" void kernel_launch(void* const* d_in, const int* in_sizes, int n_in,
                              void* d_out, int out_size) {
    const int*   row_idx = (const int*)  d_in[0];
    const int*   col_idx = (const int*)  d_in[1];
    const float* vals    = (const float*)d_in[2];
    const float* embeds  = (const float*)d_in[3];
    float*       out     = (float*)d_out;

    prep_kernel<<<(N_EDGES + 1 + 255) / 256, 256>>>(row_idx, embeds);

    gcn_spmm_kernel<<<GRID_B, WARPS_PER_BLOCK * 32>>>(row_idx, col_idx, vals,
                                                      out);
}